// round 15
// baseline (speedup 1.0000x reference)
#include <cuda_runtime.h>

#define NN   50000
#define NDIM 128
#define EDIM 32
#define HDIM 256
#define TE   64
#define TN   64
#define LDA  72   // padded leading dim; swizzle operates inside the first 64 of each row

// scratch: m_i aggregation [N, HD]
__device__ __align__(16) float g_magg[(size_t)NN * HDIM];
// duplicated-packed weights: each column stored twice -> 64-bit load = (w,w)
#define SZ_MW1 (289*512)
#define SZ_MW2 (256*512)
#define SZ_CW1 (256*512)
#define SZ_NW1 (384*512)
#define SZ_NW2 (256*256)
#define OFF_MW1 0
#define OFF_MW2 (OFF_MW1+SZ_MW1)
#define OFF_CW1 (OFF_MW2+SZ_MW2)
#define OFF_NW1 (OFF_CW1+SZ_CW1)
#define OFF_NW2 (OFF_NW1+SZ_NW1)
#define SZ_WALL (OFF_NW2+SZ_NW2)
__device__ __align__(16) float g_wd[SZ_WALL];
// 1 if edge_index buffer is int64, 0 if int32
__device__ int g_idx64;

// ---------- packed f32x2 helpers ----------
__device__ __forceinline__ unsigned long long pack2f(float lo, float hi) {
    unsigned long long r;
    asm("mov.b64 %0, {%1, %2};" : "=l"(r)
        : "r"(__float_as_uint(lo)), "r"(__float_as_uint(hi)));
    return r;
}
__device__ __forceinline__ void unpack2f(unsigned long long v, float& lo, float& hi) {
    unsigned int a, b;
    asm("mov.b64 {%0, %1}, %2;" : "=r"(a), "=r"(b) : "l"(v));
    lo = __uint_as_float(a); hi = __uint_as_float(b);
}
__device__ __forceinline__ void fma2(unsigned long long& d, unsigned long long a,
                                     unsigned long long b) {
    asm("fma.rn.f32x2 %0, %1, %2, %0;" : "+l"(d) : "l"(a), "l"(b));
}
__device__ __forceinline__ float silu_f(float v) {
    return __fdividef(v, 1.0f + __expf(-v));
}

// index accessors (dtype probed at runtime), clamped to [0, NN)
__device__ __forceinline__ int load_row(const int* __restrict__ ei32, long long i,
                                        long long E, int idx64) {
    int r = idx64 ? ei32[2*i] : ei32[i];
    return (r < 0) ? 0 : (r >= NN ? NN - 1 : r);
}
__device__ __forceinline__ int load_col(const int* __restrict__ ei32, long long i,
                                        long long E, int idx64) {
    int c = idx64 ? ei32[2*(E + i)] : ei32[E + i];
    return (c < 0) ? 0 : (c >= NN ? NN - 1 : c);
}

// swizzled smem index: row k, element e (0..63); quad-granularity rotation
__device__ __forceinline__ int swz(int k, int e) {
    return k * LDA + ((e + (((k >> 2) & 15) << 2)) & 63);
}

// ---------- tile GEMM: 8 edges (4 packed pairs) x 4 cols per thread ----------
// sA: [K][LDA] swizzled K-major shared. Wd: dup-packed weights, 512 floats (256 ull) per row.
// acc[p*4+j]: edge pair p, col c0+j.
template<int K>
__device__ __forceinline__ void mm_body(const float* sA,
                                        const float* __restrict__ Wd,
                                        int e0, int c0,
                                        unsigned long long acc[16])
{
    const unsigned long long* wb =
        reinterpret_cast<const unsigned long long*>(Wd) + c0;
    #pragma unroll 2
    for (int t = 0; t < K/4; t++) {
        int rot  = (t & 15) << 2;
        int off0 = (e0 + rot) & 63;
        int off1 = (e0 + 4 + rot) & 63;
        const float* rp = sA + t*4*LDA;
        const unsigned long long* wp = wb + (size_t)t*4*256;
        #pragma unroll
        for (int j = 0; j < 4; j++) {
            ulonglong2 a01 = *reinterpret_cast<const ulonglong2*>(rp + off0);
            ulonglong2 a23 = *reinterpret_cast<const ulonglong2*>(rp + off1);
            ulonglong2 w01 = *reinterpret_cast<const ulonglong2*>(wp);
            ulonglong2 w23 = *reinterpret_cast<const ulonglong2*>(wp + 2);
            fma2(acc[0],  a01.x, w01.x); fma2(acc[1],  a01.x, w01.y);
            fma2(acc[2],  a01.x, w23.x); fma2(acc[3],  a01.x, w23.y);
            fma2(acc[4],  a01.y, w01.x); fma2(acc[5],  a01.y, w01.y);
            fma2(acc[6],  a01.y, w23.x); fma2(acc[7],  a01.y, w23.y);
            fma2(acc[8],  a23.x, w01.x); fma2(acc[9],  a23.x, w01.y);
            fma2(acc[10], a23.x, w23.x); fma2(acc[11], a23.x, w23.y);
            fma2(acc[12], a23.y, w01.x); fma2(acc[13], a23.y, w01.y);
            fma2(acc[14], a23.y, w23.x); fma2(acc[15], a23.y, w23.y);
            rp += LDA; wp += 256;
        }
    }
    if (K & 3) {
        for (int k = K & ~3; k < K; k++) {
            int rot  = ((k >> 2) & 15) << 2;
            int off0 = (e0 + rot) & 63;
            int off1 = (e0 + 4 + rot) & 63;
            const float* rp = sA + k*LDA;
            const unsigned long long* wp = wb + (size_t)k*256;
            ulonglong2 a01 = *reinterpret_cast<const ulonglong2*>(rp + off0);
            ulonglong2 a23 = *reinterpret_cast<const ulonglong2*>(rp + off1);
            ulonglong2 w01 = *reinterpret_cast<const ulonglong2*>(wp);
            ulonglong2 w23 = *reinterpret_cast<const ulonglong2*>(wp + 2);
            fma2(acc[0],  a01.x, w01.x); fma2(acc[1],  a01.x, w01.y);
            fma2(acc[2],  a01.x, w23.x); fma2(acc[3],  a01.x, w23.y);
            fma2(acc[4],  a01.y, w01.x); fma2(acc[5],  a01.y, w01.y);
            fma2(acc[6],  a01.y, w23.x); fma2(acc[7],  a01.y, w23.y);
            fma2(acc[8],  a23.x, w01.x); fma2(acc[9],  a23.x, w01.y);
            fma2(acc[10], a23.x, w23.x); fma2(acc[11], a23.x, w23.y);
            fma2(acc[12], a23.y, w01.x); fma2(acc[13], a23.y, w01.y);
            fma2(acc[14], a23.y, w23.x); fma2(acc[15], a23.y, w23.y);
        }
    }
}

// ---------- init: dtype probe, zero m_agg, x_out = x, build dup-packed weights ----------
__global__ void init_kernel(const float* __restrict__ x, float* __restrict__ xout,
                            const int* __restrict__ ei32,
                            const float* __restrict__ mW1, const float* __restrict__ mW2,
                            const float* __restrict__ cW1, const float* __restrict__ nW1,
                            const float* __restrict__ nW2) {
    long long i = (long long)blockIdx.x * blockDim.x + threadIdx.x;
    if (i == 0) {
        int all_hi_zero = 1;
        for (int q = 0; q < 64; q++)
            if (ei32[2*q + 1] != 0) { all_hi_zero = 0; break; }
        g_idx64 = all_hi_zero;
    }
    if (i < (long long)NN * HDIM) g_magg[i] = 0.0f;
    if (i < (long long)NN * 3)    xout[i] = x[i];
    if (i < SZ_WALL) {
        long long j = i;
        if (j < SZ_MW1) {
            int k = (int)(j >> 9), c2 = (int)(j & 511);
            g_wd[OFF_MW1 + j] = mW1[k*256 + (c2 >> 1)];
        } else if ((j -= SZ_MW1) < SZ_MW2) {
            int k = (int)(j >> 9), c2 = (int)(j & 511);
            g_wd[OFF_MW2 + j] = mW2[k*256 + (c2 >> 1)];
        } else if ((j -= SZ_MW2) < SZ_CW1) {
            int k = (int)(j >> 9), c2 = (int)(j & 511);
            g_wd[OFF_CW1 + j] = cW1[k*256 + (c2 >> 1)];
        } else if ((j -= SZ_CW1) < SZ_NW1) {
            int k = (int)(j >> 9), c2 = (int)(j & 511);
            g_wd[OFF_NW1 + j] = nW1[k*256 + (c2 >> 1)];
        } else {
            j -= SZ_NW1;
            int k = (int)(j >> 8), c2 = (int)(j & 255);
            g_wd[OFF_NW2 + j] = nW2[k*128 + (c2 >> 1)];
        }
    }
}

// ---------- fused edge pipeline ----------
__global__ __launch_bounds__(512, 1)
void edge_kernel(const float* __restrict__ h, const float* __restrict__ x,
                 const int* __restrict__ ei32, const float* __restrict__ ea,
                 const float* __restrict__ mb1, const float* __restrict__ mb2,
                 const float* __restrict__ cb1, const float* __restrict__ cW2,
                 float* __restrict__ xout, long long E)
{
    extern __shared__ float sm[];
    float* s_a    = sm;                      // 289*LDA (edge_in, later m2)
    float* s_b    = sm + 289 * LDA;          // 256*LDA (m1)
    float* s_part = s_b + 256 * LDA;         // 16*8 per-warp coef partials
    float* s_dx   = s_part + 16 * 8;         // 192
    int*   s_row  = (int*)(s_dx + TE * 3);   // 64

    const int idx64 = g_idx64;
    long long base = (long long)blockIdx.x * TE;
    int tid = threadIdx.x;
    int lane = tid & 31, warp = tid >> 5;

    // --- Phase A: build edge_in [289][64] in smem (swizzled) ---
    if (tid < TE) {
        long long ge = base + tid;
        int e = tid;
        if (ge < E) {
            int r = load_row(ei32, ge, E, idx64);
            int c = load_col(ei32, ge, E, idx64);
            s_row[e] = r;
            float d0 = x[r*3+0] - x[c*3+0];
            float d1 = x[r*3+1] - x[c*3+1];
            float d2 = x[r*3+2] - x[c*3+2];
            s_dx[e*3+0] = d0; s_dx[e*3+1] = d1; s_dx[e*3+2] = d2;
            s_a[256*LDA + e] = d0*d0 + d1*d1 + d2*d2 + 1e-8f;  // row 256: rot=0
        } else {
            s_row[e] = -1;
            s_dx[e*3+0] = 0.f; s_dx[e*3+1] = 0.f; s_dx[e*3+2] = 0.f;
            s_a[256*LDA + e] = 0.f;
        }
    }
    // h[row], h[col] gather: 16 warps x 4 edges, one float4 per lane
    #pragma unroll
    for (int q = 0; q < 4; q++) {
        int e = warp*4 + q;
        long long ge = base + e; if (ge >= E) ge = E - 1;
        int r = load_row(ei32, ge, E, idx64);
        int c = load_col(ei32, ge, E, idx64);
        float4 hr = reinterpret_cast<const float4*>(h)[(size_t)r*(NDIM/4) + lane];
        float4 hc = reinterpret_cast<const float4*>(h)[(size_t)c*(NDIM/4) + lane];
        int k = lane * 4;
        int ep = (e + ((lane & 15) << 2)) & 63;   // same rot for rows k..k+3 and 128+k..
        s_a[(k+0)*LDA+ep] = hr.x; s_a[(k+1)*LDA+ep] = hr.y;
        s_a[(k+2)*LDA+ep] = hr.z; s_a[(k+3)*LDA+ep] = hr.w;
        s_a[(NDIM+k+0)*LDA+ep] = hc.x; s_a[(NDIM+k+1)*LDA+ep] = hc.y;
        s_a[(NDIM+k+2)*LDA+ep] = hc.z; s_a[(NDIM+k+3)*LDA+ep] = hc.w;
    }
    // edge_attr: 512 threads -> e=tid/8, quad=tid%8, rows 257..288 (per-element swizzle)
    {
        int e = tid >> 3, q = tid & 7;
        long long ge = base + e; if (ge >= E) ge = E - 1;
        float4 a = reinterpret_cast<const float4*>(ea)[ge*(EDIM/4) + q];
        int k = 257 + q*4;
        s_a[swz(k+0, e)] = a.x; s_a[swz(k+1, e)] = a.y;
        s_a[swz(k+2, e)] = a.z; s_a[swz(k+3, e)] = a.w;
    }
    __syncthreads();

    int eg = tid >> 6;          // 0..7  edge group (8 edges)
    int cg = tid & 63;          // 0..63 col group (4 cols)
    int e0 = eg * 8;
    int c0 = cg * 4;
    int crot = (cg & 15) << 2;  // epilogue swizzle rot for rows c0..c0+3

    unsigned long long acc[16];

    // --- GEMM1: m1 = silu(edge_in @ mW1 + mb1), K=289 ---
    #pragma unroll
    for (int i = 0; i < 16; i++) acc[i] = 0ull;
    mm_body<2*NDIM + 1 + EDIM>(s_a, g_wd + OFF_MW1, e0, c0, acc);
    {
        float bb[4] = { mb1[c0], mb1[c0+1], mb1[c0+2], mb1[c0+3] };
        #pragma unroll
        for (int p = 0; p < 4; p++) {
            int ep = ((e0 + 2*p) + crot) & 63;
            #pragma unroll
            for (int j = 0; j < 4; j++) {
                float lo, hi; unpack2f(acc[p*4+j], lo, hi);
                *reinterpret_cast<unsigned long long*>(&s_b[(c0+j)*LDA + ep]) =
                    pack2f(silu_f(lo + bb[j]), silu_f(hi + bb[j]));
            }
        }
    }
    __syncthreads();

    // --- GEMM2: m2 = silu(m1 @ mW2 + mb2), K=256; store to s_a + aggregate m_i ---
    #pragma unroll
    for (int i = 0; i < 16; i++) acc[i] = 0ull;
    mm_body<HDIM>(s_b, g_wd + OFF_MW2, e0, c0, acc);
    {
        float bb[4] = { mb2[c0], mb2[c0+1], mb2[c0+2], mb2[c0+3] };
        #pragma unroll
        for (int p = 0; p < 4; p++) {
            int e = e0 + 2*p;
            int ep = (e + crot) & 63;
            int r0 = s_row[e], r1 = s_row[e+1];
            #pragma unroll
            for (int j = 0; j < 4; j++) {
                float lo, hi; unpack2f(acc[p*4+j], lo, hi);
                float v0 = silu_f(lo + bb[j]);
                float v1 = silu_f(hi + bb[j]);
                *reinterpret_cast<unsigned long long*>(&s_a[(c0+j)*LDA + ep]) =
                    pack2f(v0, v1);
                if (r0 >= 0) atomicAdd(&g_magg[(size_t)r0*HDIM + c0 + j], v0);
                if (r1 >= 0) atomicAdd(&g_magg[(size_t)r1*HDIM + c0 + j], v1);
            }
        }
    }
    __syncthreads();

    // --- GEMM3: c1 = silu(m2 @ cW1 + cb1); coef = c1 @ cW2 (shuffle-reduced) ---
    #pragma unroll
    for (int i = 0; i < 16; i++) acc[i] = 0ull;
    mm_body<HDIM>(s_a, g_wd + OFF_CW1, e0, c0, acc);
    {
        float bb[4] = { cb1[c0], cb1[c0+1], cb1[c0+2], cb1[c0+3] };
        float wv[4] = { cW2[c0], cW2[c0+1], cW2[c0+2], cW2[c0+3] };
        float pe[8];
        #pragma unroll
        for (int q = 0; q < 8; q++) pe[q] = 0.f;
        #pragma unroll
        for (int p = 0; p < 4; p++) {
            #pragma unroll
            for (int j = 0; j < 4; j++) {
                float lo, hi; unpack2f(acc[p*4+j], lo, hi);
                pe[2*p]   += silu_f(lo + bb[j]) * wv[j];
                pe[2*p+1] += silu_f(hi + bb[j]) * wv[j];
            }
        }
        #pragma unroll
        for (int o = 16; o > 0; o >>= 1) {
            #pragma unroll
            for (int q = 0; q < 8; q++)
                pe[q] += __shfl_xor_sync(0xffffffffu, pe[q], o);
        }
        if (lane == 0) {
            #pragma unroll
            for (int q = 0; q < 8; q++) s_part[warp*8 + q] = pe[q];
        }
    }
    __syncthreads();

    // --- x aggregation: coef[e] = s_part[2*eg][q] + s_part[2*eg+1][q] ---
    if (tid < TE) {
        int e = tid; int r = s_row[e];
        if (r >= 0) {
            int egg = e >> 3, q = e & 7;
            float cf = s_part[egg*16 + q] + s_part[egg*16 + 8 + q];
            atomicAdd(&xout[r*3+0], cf * s_dx[e*3+0]);
            atomicAdd(&xout[r*3+1], cf * s_dx[e*3+1]);
            atomicAdd(&xout[r*3+2], cf * s_dx[e*3+2]);
        }
    }
}

// ---------- fused node MLP + residual + LayerNorm ----------
__global__ __launch_bounds__(512, 1)
void node_kernel(const float* __restrict__ h,
                 const float* __restrict__ nb1, const float* __restrict__ nb2,
                 const float* __restrict__ gamma, const float* __restrict__ beta,
                 float* __restrict__ hout)
{
    extern __shared__ float sm[];
    float* s_a   = sm;                    // 384*LDA  (h_in swizzled; rows<128 = h residual)
    float* s_b   = sm + 384 * LDA;        // 256*LDA  (t, swizzled)
    float* s_res = s_a + NDIM * LDA;      // overlay onto s_a rows >= 128 (64*128 floats)

    int tid = threadIdx.x, lane = tid & 31, warp = tid >> 5;
    int n0 = blockIdx.x * TN;

    // load h_in = [h(128) ; m_agg(256)] K-major, swizzled
    #pragma unroll
    for (int q = 0; q < 4; q++) {
        int e = warp*4 + q;
        int n = n0 + e; if (n >= NN) n = NN - 1;
        float4 hv = reinterpret_cast<const float4*>(h)[(size_t)n*(NDIM/4) + lane];
        int k = lane * 4;
        int ep = (e + ((lane & 15) << 2)) & 63;  // rows k, 128+k, 256+k share rot
        s_a[(k+0)*LDA+ep] = hv.x; s_a[(k+1)*LDA+ep] = hv.y;
        s_a[(k+2)*LDA+ep] = hv.z; s_a[(k+3)*LDA+ep] = hv.w;
        float4 m0 = reinterpret_cast<const float4*>(g_magg)[(size_t)n*(HDIM/4) + lane];
        float4 m1 = reinterpret_cast<const float4*>(g_magg)[(size_t)n*(HDIM/4) + lane + 32];
        int k0 = NDIM + k;
        s_a[(k0+0)*LDA+ep] = m0.x; s_a[(k0+1)*LDA+ep] = m0.y;
        s_a[(k0+2)*LDA+ep] = m0.z; s_a[(k0+3)*LDA+ep] = m0.w;
        int k1 = NDIM + 128 + k;
        s_a[(k1+0)*LDA+ep] = m1.x; s_a[(k1+1)*LDA+ep] = m1.y;
        s_a[(k1+2)*LDA+ep] = m1.z; s_a[(k1+3)*LDA+ep] = m1.w;
    }
    __syncthreads();

    int eg = tid >> 6, cg = tid & 63;
    int e0 = eg * 8, c0 = cg * 4;
    int crot = (cg & 15) << 2;

    // GEMM1: t = silu(h_in @ nW1 + nb1), K=384, 256 cols
    unsigned long long acc[16];
    #pragma unroll
    for (int i = 0; i < 16; i++) acc[i] = 0ull;
    mm_body<NDIM + HDIM>(s_a, g_wd + OFF_NW1, e0, c0, acc);
    {
        float bb[4] = { nb1[c0], nb1[c0+1], nb1[c0+2], nb1[c0+3] };
        #pragma unroll
        for (int p = 0; p < 4; p++) {
            int ep = ((e0 + 2*p) + crot) & 63;
            #pragma unroll
            for (int j = 0; j < 4; j++) {
                float lo, hi; unpack2f(acc[p*4+j], lo, hi);
                *reinterpret_cast<unsigned long long*>(&s_b[(c0+j)*LDA + ep]) =
                    pack2f(silu_f(lo + bb[j]), silu_f(hi + bb[j]));
            }
        }
    }
    __syncthreads();

    // GEMM2: h_res = h + t @ nW2 + nb2 ; K=256, 128 cols (2 cols/thread), swizzled reads
    {
        int c20 = cg * 2;
        unsigned long long a2[8];
        #pragma unroll
        for (int i = 0; i < 8; i++) a2[i] = 0ull;
        const unsigned long long* wb =
            reinterpret_cast<const unsigned long long*>(g_wd + OFF_NW2) + c20;
        #pragma unroll 2
        for (int t = 0; t < 64; t++) {
            int rot  = (t & 15) << 2;
            int off0 = (e0 + rot) & 63;
            int off1 = (e0 + 4 + rot) & 63;
            const float* rp = s_b + t*4*LDA;
            const unsigned long long* wp = wb + (size_t)t*4*128;
            #pragma unroll
            for (int j = 0; j < 4; j++) {
                ulonglong2 a01 = *reinterpret_cast<const ulonglong2*>(rp + off0);
                ulonglong2 a23 = *reinterpret_cast<const ulonglong2*>(rp + off1);
                ulonglong2 wv = *reinterpret_cast<const ulonglong2*>(wp);
                fma2(a2[0], a01.x, wv.x); fma2(a2[1], a01.x, wv.y);
                fma2(a2[2], a01.y, wv.x); fma2(a2[3], a01.y, wv.y);
                fma2(a2[4], a23.x, wv.x); fma2(a2[5], a23.x, wv.y);
                fma2(a2[6], a23.y, wv.x); fma2(a2[7], a23.y, wv.y);
                rp += LDA; wp += 128;
            }
        }
        float bz0 = nb2[c20], bz1 = nb2[c20+1];
        #pragma unroll
        for (int p = 0; p < 4; p++) {
            int e = e0 + 2*p;
            // residual h lives in s_a rows c20 (<128), swizzled with rot of row c20
            int hrot = ((c20 >> 2) & 15) << 2;
            int ep = (e + hrot) & 63;
            float lo, hi;
            unpack2f(a2[p*2+0], lo, hi);
            s_res[e*NDIM + c20]       = s_a[c20*LDA + ep]       + lo + bz0;
            s_res[(e+1)*NDIM + c20]   = s_a[c20*LDA + ep + 1]   + hi + bz0;
            unpack2f(a2[p*2+1], lo, hi);
            s_res[e*NDIM + c20+1]     = s_a[(c20+1)*LDA + ep]     + lo + bz1;
            s_res[(e+1)*NDIM + c20+1] = s_a[(c20+1)*LDA + ep + 1] + hi + bz1;
        }
    }
    __syncthreads();

    // LayerNorm per node (warp per 4 nodes, 1 float4 per lane)
    #pragma unroll
    for (int q = 0; q < 4; q++) {
        int e = warp*4 + q;
        int n = n0 + e;
        float4 v = reinterpret_cast<const float4*>(s_res + e*NDIM)[lane];
        float s  = v.x + v.y + v.z + v.w;
        float sq = v.x*v.x + v.y*v.y + v.z*v.z + v.w*v.w;
        #pragma unroll
        for (int o = 16; o > 0; o >>= 1) {
            s  += __shfl_xor_sync(0xffffffffu, s,  o);
            sq += __shfl_xor_sync(0xffffffffu, sq, o);
        }
        float mu   = s * (1.0f / NDIM);
        float var  = sq * (1.0f / NDIM) - mu * mu;
        float rstd = rsqrtf(var + 1e-5f);
        if (n < NN) {
            float4 g  = reinterpret_cast<const float4*>(gamma)[lane];
            float4 be = reinterpret_cast<const float4*>(beta)[lane];
            float4 o;
            o.x = (v.x - mu) * rstd * g.x + be.x;
            o.y = (v.y - mu) * rstd * g.y + be.y;
            o.z = (v.z - mu) * rstd * g.z + be.z;
            o.w = (v.w - mu) * rstd * g.w + be.w;
            reinterpret_cast<float4*>(hout + (size_t)n * NDIM)[lane] = o;
        }
    }
}

extern "C" void kernel_launch(void* const* d_in, const int* in_sizes, int n_in,
                              void* d_out, int out_size)
{
    const float* h   = (const float*)d_in[0];
    const float* x   = (const float*)d_in[1];
    const int*   ei32 = (const int*)d_in[2];     // int32 OR int64 (probed at runtime)
    const float* ea  = (const float*)d_in[3];
    const float* mW1 = (const float*)d_in[4];
    const float* mb1 = (const float*)d_in[5];
    const float* mW2 = (const float*)d_in[6];
    const float* mb2 = (const float*)d_in[7];
    const float* nW1 = (const float*)d_in[8];
    const float* nb1 = (const float*)d_in[9];
    const float* nW2 = (const float*)d_in[10];
    const float* nb2 = (const float*)d_in[11];
    const float* cW1 = (const float*)d_in[12];
    const float* cb1 = (const float*)d_in[13];
    const float* cW2 = (const float*)d_in[14];
    const float* gamma = (const float*)d_in[15];
    const float* beta  = (const float*)d_in[16];

    float* hout = (float*)d_out;
    float* xout = hout + (size_t)NN * NDIM;
    long long E = (long long)in_sizes[2] / 2;    // element count / 2, dtype-independent

    const int edge_smem = (289*LDA + 256*LDA + 16*8 + TE*3 + TE) * 4;   // ~158.5 KB
    const int node_smem = ((NDIM+HDIM)*LDA + HDIM*LDA) * 4;             // ~184 KB
    cudaFuncSetAttribute(edge_kernel, cudaFuncAttributeMaxDynamicSharedMemorySize, edge_smem);
    cudaFuncSetAttribute(node_kernel, cudaFuncAttributeMaxDynamicSharedMemorySize, node_smem);

    {
        long long tot = (long long)NN * HDIM;
        int blocks = (int)((tot + 511) / 512);
        init_kernel<<<blocks, 512>>>(x, xout, ei32, mW1, mW2, cW1, nW1, nW2);
    }
    {
        int blocks = (int)((E + TE - 1) / TE);
        edge_kernel<<<blocks, 512, edge_smem>>>(h, x, ei32, ea, mb1, mb2,
                                                cb1, cW2, xout, E);
    }
    {
        int blocks = (NN + TN - 1) / TN;
        node_kernel<<<blocks, 512, node_smem>>>(h, nb1, nb2, gamma, beta, hout);
    }
}